// round 1
// baseline (speedup 1.0000x reference)
#include <cuda_runtime.h>
#include <math.h>

// Problem constants
#define HH 200
#define WW 352
#define HW 70400           // HH*WW
#define BX 32              // spatial tile width
#define BY 8               // spatial tile height
#define CO_B 32            // couts per block
#define CC 8               // cin chunk

// Scratch (static device memory — allocation-free per harness rules)
__device__ float g_cat[4 * 128 * HW];   // cat_feat: (B=4, 2C=128, H, W)
__device__ float g_gates[128 * HW];     // gates for current step
__device__ float g_rh[64 * HW];         // reset * h

// Generic fused 3x3 SAME conv over a virtual channel-concat [in0 (cin0 ch), in1 (cin1 ch)].
// mode 0: out = 0.5*(auxA + conv+b)   (message/agg); also copies auxA into out2 (x0 -> cat_feat)
// mode 1: out = sigmoid(conv+b)       (gates)
// mode 2: out = (1-u)*h + u*tanh(conv+b), u = auxA, h = auxB (may be null -> 0)
__global__ __launch_bounds__(256) void conv3x3_k(
    const float* __restrict__ in0, int cin0,
    const float* __restrict__ in1, int cin1,
    const float* __restrict__ wgt, int wcin,
    const float* __restrict__ bias,
    float* __restrict__ out,
    int mode,
    const float* __restrict__ auxA,
    const float* __restrict__ auxB,
    float* __restrict__ out2)
{
    __shared__ float s_in[CC][BY + 2][36];   // padded row stride 36 floats (16B-aligned rows)
    __shared__ float s_w[CO_B][CC][12];      // 9 weights padded to 12 for float4 loads

    const int tid  = threadIdx.x;
    const int cog  = tid >> 6;          // 0..3  (cout subgroup of 8)
    const int pxg  = tid & 63;          // 0..63 (pixel group of 4)
    const int prow = pxg >> 3;          // 0..7
    const int pcol = (pxg & 7) << 2;    // 0,4,...,28

    const int bx = blockIdx.x, by = blockIdx.y, cob = blockIdx.z;
    const int ox = bx * BX - 1, oy = by * BY - 1;

    float acc[8][4];
#pragma unroll
    for (int i = 0; i < 8; i++)
#pragma unroll
        for (int j = 0; j < 4; j++) acc[i][j] = 0.f;

    const int cin_eff = in1 ? (cin0 + cin1) : cin0;
    const int nchunks = cin_eff / CC;

    for (int ch = 0; ch < nchunks; ch++) {
        // ---- stage input tile (with SAME zero padding) ----
        for (int idx = tid; idx < CC * 10 * 34; idx += 256) {
            int c   = idx / 340;
            int rem = idx - c * 340;
            int r   = rem / 34;
            int col = rem - r * 34;
            int gy = oy + r, gx = ox + col;
            float v = 0.f;
            if ((unsigned)gy < (unsigned)HH && (unsigned)gx < (unsigned)WW) {
                int gc = ch * CC + c;
                const float* src = (gc < cin0) ? (in0 + (size_t)gc * HW)
                                               : (in1 + (size_t)(gc - cin0) * HW);
                v = src[gy * WW + gx];
            }
            s_in[c][r][col] = v;
        }
        // ---- stage weights ----
        for (int idx = tid; idx < CO_B * CC * 9; idx += 256) {
            int co  = idx / 72;
            int rem = idx - co * 72;
            int c   = rem / 9;
            int k   = rem - c * 9;
            s_w[co][c][k] =
                wgt[((size_t)(cob * CO_B + co) * wcin + ch * CC + c) * 9 + k];
        }
        __syncthreads();

        // ---- compute: 288 FFMA per cin per thread, ~30 LDS ----
#pragma unroll
        for (int c = 0; c < CC; c++) {
            float4 a0 = *(const float4*)&s_in[c][prow + 0][pcol];
            float2 b0 = *(const float2*)&s_in[c][prow + 0][pcol + 4];
            float4 a1 = *(const float4*)&s_in[c][prow + 1][pcol];
            float2 b1 = *(const float2*)&s_in[c][prow + 1][pcol + 4];
            float4 a2 = *(const float4*)&s_in[c][prow + 2][pcol];
            float2 b2 = *(const float2*)&s_in[c][prow + 2][pcol + 4];
            float v0[6] = {a0.x, a0.y, a0.z, a0.w, b0.x, b0.y};
            float v1[6] = {a1.x, a1.y, a1.z, a1.w, b1.x, b1.y};
            float v2[6] = {a2.x, a2.y, a2.z, a2.w, b2.x, b2.y};
#pragma unroll
            for (int co = 0; co < 8; co++) {
                const float* wp = &s_w[cog * 8 + co][c][0];
                float4 w0 = *(const float4*)(wp);
                float4 w1 = *(const float4*)(wp + 4);
                float4 w2 = *(const float4*)(wp + 8);   // only .x used (k=8)
#pragma unroll
                for (int p = 0; p < 4; p++) {
                    float s = acc[co][p];
                    s += v0[p + 0] * w0.x; s += v0[p + 1] * w0.y; s += v0[p + 2] * w0.z;
                    s += v1[p + 0] * w0.w; s += v1[p + 1] * w1.x; s += v1[p + 2] * w1.y;
                    s += v2[p + 0] * w1.z; s += v2[p + 1] * w1.w; s += v2[p + 2] * w2.x;
                    acc[co][p] = s;
                }
            }
        }
        __syncthreads();
    }

    // ---- epilogue ----
    const int y  = by * BY + prow;        // H=200 divisible by 8, no bounds check
    const int xb = bx * BX + pcol;        // W=352 divisible by 32
#pragma unroll
    for (int co = 0; co < 8; co++) {
        const int oc = cob * CO_B + cog * 8 + co;
        const float bia = bias[oc];
        const size_t base = (size_t)oc * HW + (size_t)y * WW + xb;
#pragma unroll
        for (int p = 0; p < 4; p++) {
            float v = acc[co][p] + bia;
            size_t o = base + p;
            if (mode == 0) {
                float x0v = auxA[o];
                out[o]  = 0.5f * (x0v + v);
                out2[o] = x0v;
            } else if (mode == 1) {
                out[o] = 1.f / (1.f + expf(-v));
            } else {
                float u  = auxA[o];
                float hp = auxB ? auxB[o] : 0.f;
                out[o] = (1.f - u) * hp + u * tanhf(v);
            }
        }
    }
}

// rh = reset * h  (vectorized)
__global__ void rh_k(const float4* __restrict__ g, const float4* __restrict__ h,
                     float4* __restrict__ rh, int n4)
{
    int i = blockIdx.x * blockDim.x + threadIdx.x;
    if (i < n4) {
        float4 a = g[i], b = h[i];
        float4 r;
        r.x = a.x * b.x; r.y = a.y * b.y; r.z = a.z * b.z; r.w = a.w * b.w;
        rh[i] = r;
    }
}

extern "C" void kernel_launch(void* const* d_in, const int* in_sizes, int n_in,
                              void* d_out, int out_size)
{
    const float* x       = (const float*)d_in[0]; // (2,4,64,200,352)
    const float* msg_w   = (const float*)d_in[1]; // (64,128,3,3)
    const float* msg_b   = (const float*)d_in[2]; // (64)
    const float* gates_w = (const float*)d_in[3]; // (128,192,3,3)
    const float* gates_b = (const float*)d_in[4]; // (128)
    const float* can_w   = (const float*)d_in[5]; // (64,192,3,3)
    const float* can_b   = (const float*)d_in[6]; // (64)
    float* out = (float*)d_out;                   // (4,64,200,352)

    float *cat, *gates, *rh;
    cudaGetSymbolAddress((void**)&cat,   g_cat);
    cudaGetSymbolAddress((void**)&gates, g_gates);
    cudaGetSymbolAddress((void**)&rh,    g_rh);

    dim3 block(256);
    dim3 gridMsg(WW / BX, HH / BY, 64  / CO_B);  // 11 x 25 x 2
    dim3 gridG  (WW / BX, HH / BY, 128 / CO_B);  // 11 x 25 x 4
    dim3 gridC  (WW / BX, HH / BY, 64  / CO_B);  // 11 x 25 x 2

    // Phase A: message conv + agg + cat_feat build (per batch image)
    for (int b = 0; b < 4; b++) {
        const float* x0b = x + (size_t)b * 64 * HW;          // agent 0, batch b
        const float* x1b = x + (size_t)(4 + b) * 64 * HW;    // agent 1, batch b
        float* cat_b = cat + (size_t)b * 128 * HW;
        conv3x3_k<<<gridMsg, block>>>(
            x0b, 64, x1b, 64, msg_w, 128, msg_b,
            cat_b + (size_t)64 * HW,       // agg -> channels 64..127
            0, x0b, nullptr,
            cat_b);                        // x0 copy -> channels 0..63
    }

    // Phase B: sequential ConvGRU, 4 steps; h chains through d_out slices
    for (int t = 0; t < 4; t++) {
        const float* inp = cat + (size_t)t * 128 * HW;
        const float* hp  = t ? (out + (size_t)(t - 1) * 64 * HW) : nullptr;

        // gates = sigmoid(conv([inp, h]))
        conv3x3_k<<<gridG, block>>>(
            inp, 128, hp, 64, gates_w, 192, gates_b,
            gates, 1, nullptr, nullptr, nullptr);

        // rh = reset * h
        if (t) {
            int n4 = 64 * HW / 4;
            rh_k<<<(n4 + 255) / 256, 256>>>(
                (const float4*)gates, (const float4*)hp, (float4*)rh, n4);
        }

        // cnm = tanh(conv([inp, rh])); h_next = (1-u)*h + u*cnm  -> out[t]
        conv3x3_k<<<gridC, block>>>(
            inp, 128, t ? rh : nullptr, 64, can_w, 192, can_b,
            out + (size_t)t * 64 * HW,
            2, gates + (size_t)64 * HW, hp, nullptr);
    }
}